// round 6
// baseline (speedup 1.0000x reference)
#include <cuda_runtime.h>
#include <cuda_bf16.h>

#define NN     800
#define CC     64
#define TRS    40
#define SPT    10
#define BUF    120
#define TT     400
#define ROUNDS 200
#define NBLK   100
#define RPB    8
#define THREADS 256
#define KPL    25
#define D0ROW  24          // cap d0 entries per row (Poisson(6.67) tail ~1e-8)
#define SLOTCAP 192        // recon slots per block (mean ~107, +8 sigma)
#define HBYTES (BUF * NN * 2)
#define DT     1e-4f
#define GK     5.0f        // KG*KI

// ---------------- static device scratch -------------------------------------
__device__ __align__(16) __nv_bfloat16 g_HT0[BUF * NN];
__device__ __align__(16) float g_XTR[TRS * NN];
__device__ __align__(16) float g_Xpub[2][2 * NN];   // [parity][x(a)|x(b)]
__device__ __align__(16) float g_XPpub[2][NN];      // [parity][x_pre(next a)]
__device__ int   g_ctr[ROUNDS];
__device__ float g_rowsum[NN];
__device__ float g_rowsq[NN];
__device__ float g_invnorm;
__device__ int   g_flag64;
__device__ int   g_d0n[NN];                         // global d0 table (CSR-ish, fixed stride)
__device__ short g_d0k[NN * D0ROW];
__device__ __nv_bfloat16 g_d0w[NN * D0ROW];

__device__ __forceinline__ int ld_acq(const int* p) {
    int v;
    asm volatile("ld.global.acquire.gpu.s32 %0, [%1];" : "=r"(v) : "l"(p) : "memory");
    return v;
}
__device__ __forceinline__ void red_release(int* p) {
    asm volatile("red.release.gpu.global.add.s32 [%0], 1;" :: "l"(p) : "memory");
}
__device__ __forceinline__ float warp_sum(float v) {
    #pragma unroll
    for (int o = 16; o; o >>= 1) v += __shfl_xor_sync(0xffffffffu, v, o);
    return v;
}

// ---------------- per-row stats ----------------------------------------------
__global__ void k_rowstats(const float* __restrict__ sc) {
    int i = blockIdx.x, tid = threadIdx.x;
    float s1 = 0.f, s2 = 0.f;
    for (int j = tid; j < NN; j += 128) {
        float v = sc[i * NN + j];
        s1 += fabsf(v); s2 += v * v;
    }
    s1 = warp_sum(s1); s2 = warp_sum(s2);
    __shared__ float sh1[4], sh2[4];
    if ((tid & 31) == 0) { sh1[tid >> 5] = s1; sh2[tid >> 5] = s2; }
    __syncthreads();
    if (tid == 0) {
        g_rowsum[i] = sh1[0] + sh1[1] + sh1[2] + sh1[3];
        g_rowsq[i]  = sh2[0] + sh2[1] + sh2[2] + sh2[3];
    }
}

__global__ void k_norm() {
    int tid = threadIdx.x;
    float s = 0.f;
    for (int i = tid; i < NN; i += 256) s += g_rowsq[i];
    s = warp_sum(s);
    __shared__ float sh[8];
    if ((tid & 31) == 0) sh[tid >> 5] = s;
    __syncthreads();
    if (tid == 0) {
        float tot = 0.f;
        #pragma unroll
        for (int w = 0; w < 8; w++) tot += sh[w];
        g_invnorm = rsqrtf(tot);
    }
}

// ---------------- prep: history transpose, seed buffers, dtype detect --------
__global__ void k_prep2(const float* __restrict__ hE, const void* __restrict__ delays) {
    int g = blockIdx.x * blockDim.x + threadIdx.x;
    if (g < BUF * NN) {
        int m = g / NN, j = g % NN;
        g_HT0[g] = __float2bfloat16(hE[j * BUF + (BUF - 1 - m)]);  // slot m = x(m-BUF)
    }
    if (g < NN) {
        g_Xpub[1][g]      = hE[g * BUF + 1];   // x(-2)
        g_Xpub[1][NN + g] = hE[g * BUF + 0];   // x(-1)
    }
    if (g < ROUNDS) g_ctr[g] = 0;
    if (g == 0) {
        const int* p = (const int*)delays;
        int any = 0;
        for (int k = 0; k < 100; k++) any |= p[2 * k + 1];
        g_flag64 = (any == 0) ? 1 : 0;
    }
}

// ---------------- global d0 table (deterministic, per-row serial) ------------
__global__ void k_d0tab(const float* __restrict__ sc, const void* __restrict__ delays) {
    int j = blockIdx.x * blockDim.x + threadIdx.x;
    if (j >= NN) return;
    const int* dp = (const int*)delays;
    const int f64 = g_flag64;
    int n = 0;
    for (int k = 0; k < NN; k++) {
        int e = j * NN + k;
        int d = f64 ? dp[2 * e] : dp[e];
        if (d == 0 && n < D0ROW) {
            g_d0k[j * D0ROW + n] = (short)k;
            g_d0w[j * D0ROW + n] = __float2bfloat16(fabsf(sc[e]));
            n++;
        }
    }
    g_d0n[j] = n;
}

// ---------------- x_pre(0) for all rows --------------------------------------
__global__ void k_xpre0(const float* __restrict__ hE, const float* __restrict__ hx,
                        const float* __restrict__ sc, const float* __restrict__ noise,
                        const float* __restrict__ external, const void* __restrict__ delays) {
    int i = blockIdx.x, tid = threadIdx.x;
    const int* dp = (const int*)delays;
    const int f64 = g_flag64;
    float s = 0.f;
    for (int j = tid; j < NN; j += 256) {
        int e = i * NN + j;
        int d = f64 ? dp[2 * e] : dp[e];
        if (d >= 1) s += fabsf(sc[e]) * hE[j * BUF + d];   // x(-1-d) = hE[j][d]
    }
    s = warp_sum(s);
    __shared__ float sh[8];
    if ((tid & 31) == 0) sh[tid >> 5] = s;
    __syncthreads();
    if (tid == 0) {
        float tot = 0.f;
        #pragma unroll
        for (int w = 0; w < 8; w++) tot += sh[w];
        float Gn = 500.f * g_invnorm, grs = Gn * g_rowsum[i];
        float x0 = hx[2 * i], y0 = hx[2 * i + 1];
        float r2 = x0 * x0 + y0 * y0;
        float u  = external[i * (SPT * TRS)];      // t=0
        float nsx = noise[2 * i];
        float dxp = (-0.5f - r2) * x0 - 10.f * y0 + Gn * tot - grs * x0 + GK * u;
        g_XPpub[1][i] = x0 + DT * dxp + nsx;
    }
}

// ---------------- main: 2 steps per sync round --------------------------------
__global__ void __launch_bounds__(THREADS, 1)
k_main(const float* __restrict__ external, const float* __restrict__ hx,
       const float* __restrict__ sc, const float* __restrict__ noise,
       const void* __restrict__ delays) {
    extern __shared__ __align__(16) unsigned char smem_raw[];
    __nv_bfloat16* Hs  = (__nv_bfloat16*)smem_raw;                     // [BUF][NN]
    float* XPs         = (float*)(smem_raw + HBYTES);                  // [NN]
    int*   j0_sh       = (int*)(XPs + NN);                             // [RPB*32]
    float* w0_sh       = (float*)(j0_sh + RPB * 32);
    int*   j1_sh       = (int*)(w0_sh + RPB * 32);
    float* w1_sh       = (float*)(j1_sh + RPB * 32);
    int*   cnt_sh      = (int*)(w1_sh + RPB * 32);                     // n0[RPB], n1[RPB]
    int*   tabn        = cnt_sh + 2 * RPB;                             // [SLOTCAP]
    short* tabk        = (short*)(tabn + SLOTCAP);                     // [SLOTCAP*D0ROW]
    __nv_bfloat16* tabw = (__nv_bfloat16*)(tabk + SLOTCAP * D0ROW);    // [SLOTCAP*D0ROW]

    const int tid  = threadIdx.x;
    const int lane = tid & 31;
    const int wrp  = tid >> 5;
    const int i    = blockIdx.x * RPB + wrp;

    // stage history
    {
        const uint4* src = (const uint4*)g_HT0;
        uint4* dst = (uint4*)Hs;
        for (int idx = tid; idx < HBYTES / 16; idx += THREADS) dst[idx] = src[idx];
    }

    // build weights, delay offsets, d0/d1 lists (deterministic ballot compaction)
    float wreg[KPL];
    int   dNN[KPL];
    unsigned mask1 = 0;       // bits k where this lane's term has d==1
    int n0 = 0, n1 = 0;
    const int f64 = g_flag64;
    const int* dp = (const int*)delays;
    #pragma unroll
    for (int k = 0; k < KPL; k++) {
        int j = lane + 32 * k;
        int e = i * NN + j;
        float w = fabsf(sc[e]);
        int d = f64 ? dp[2 * e] : dp[e];
        unsigned b0 = __ballot_sync(0xffffffffu, d == 0);
        unsigned b1 = __ballot_sync(0xffffffffu, d == 1);
        if (d == 0) {
            int pos = n0 + __popc(b0 & ((1u << lane) - 1));
            if (pos < 32) { j0_sh[wrp * 32 + pos] = j; w0_sh[wrp * 32 + pos] = w; }
            wreg[k] = 0.f; dNN[k] = NN;
        } else {
            wreg[k] = w; dNN[k] = d * NN;
        }
        if (d == 1) {
            int pos = n1 + __popc(b1 & ((1u << lane) - 1));
            if (pos < 32) { j1_sh[wrp * 32 + pos] = j; w1_sh[wrp * 32 + pos] = w; }
            mask1 |= (1u << k);
        }
        n0 += __popc(b0); n1 += __popc(b1);
    }
    if (n0 > 32) n0 = 32;
    if (n1 > 32) n1 = 32;
    if (lane == 0) { cnt_sh[wrp] = n0; cnt_sh[RPB + wrp] = n1; }
    __syncthreads();

    int wb = 0;
    for (int w = 0; w < wrp; w++) wb += cnt_sh[w] + cnt_sh[RPB + w];
    const int slot0 = wb + lane;
    const int slot1 = wb + n0 + lane;

    int   j0r = 0; float w0r = 0.f;
    int   j1r = 0; float w1r = 0.f;
    if (lane < n0) { j0r = j0_sh[wrp * 32 + lane]; w0r = w0_sh[wrp * 32 + lane]; }
    if (lane < n1) { j1r = j1_sh[wrp * 32 + lane]; w1r = w1_sh[wrp * 32 + lane]; }

    // fill recon table segments for my entries
    if (lane < n0 && slot0 < SLOTCAP) {
        int n = g_d0n[j0r]; if (n > D0ROW) n = D0ROW;
        tabn[slot0] = n;
        for (int m = 0; m < n; m++) {
            tabk[slot0 * D0ROW + m] = g_d0k[j0r * D0ROW + m];
            tabw[slot0 * D0ROW + m] = g_d0w[j0r * D0ROW + m];
        }
    }
    if (lane < n1 && slot1 < SLOTCAP) {
        int n = g_d0n[j1r]; if (n > D0ROW) n = D0ROW;
        tabn[slot1] = n;
        for (int m = 0; m < n; m++) {
            tabk[slot1 * D0ROW + m] = g_d0k[j1r * D0ROW + m];
            tabw[slot1 * D0ROW + m] = g_d0w[j1r * D0ROW + m];
        }
    }
    __syncthreads();

    const float Gn    = 500.0f * g_invnorm;
    const float grs   = Gn * g_rowsum[i];
    const float kappa = DT * Gn;
    float x = hx[2 * i], y = hx[2 * i + 1];

    // prologue: inputs for t=0,1,2 and partial gather for step 0 (d>=2 only)
    float uA = __ldg(&external[i * (SPT * TRS) + 0]);                      // t=0
    float uB = __ldg(&external[i * (SPT * TRS) + 1 * TRS + 0]);            // t=1
    float uN = __ldg(&external[i * (SPT * TRS) + 2 * TRS + 0]);            // t=2
    float2 nsA = *(const float2*)&noise[(size_t)0 * 2 * NN + 2 * i];
    float2 nsB = *(const float2*)&noise[(size_t)1 * 2 * NN + 2 * i];
    float2 nsN = *(const float2*)&noise[(size_t)2 * 2 * NN + 2 * i];
    float pre_a;
    {
        const int baseN = (BUF - 1) * NN;        // slot(-1)
        float acc0 = 0.f, acc1 = 0.f;
        #pragma unroll
        for (int k = 0; k < KPL; k++) {
            float w2 = ((mask1 >> k) & 1u) ? 0.f : wreg[k];
            int sN = baseN - dNN[k];
            if (sN < 0) sN += BUF * NN;
            float h = __bfloat162float(Hs[sN + lane + 32 * k]);
            if (k & 1) acc1 = fmaf(w2, h, acc1); else acc0 = fmaf(w2, h, acc0);
        }
        pre_a = warp_sum(acc0 + acc1);
    }

    for (int r = 0; r < ROUNDS; r++) {
        const int a = 2 * r, b = a + 1;
        const int par = r & 1, parp = par ^ 1;
        const int s2 = (a - 2 + BUF) % BUF;      // slot(a-2)
        const int s1 = (a - 1 + BUF) % BUF;      // slot(a-1)
        const int s2N = s2 * NN, s1N = s1 * NN;

        // ---- spin for previous round ----
        if (r) while (ld_acq(&g_ctr[r - 1]) < NBLK) { }

        // ---- bulk load + append x(a-2), x(a-1); stage XP[a] ----
        {
            const float* X2 = g_Xpub[parp];
            const float* XP = g_XPpub[parp];
            for (int idx = tid; idx < NN / 4; idx += THREADS) {
                float4 v2 = __ldcg((const float4*)X2 + idx);
                float4 v1 = __ldcg((const float4*)(X2 + NN) + idx);
                float4 vp = __ldcg((const float4*)XP + idx);
                __nv_bfloat162* d2 = (__nv_bfloat162*)(Hs + s2N) + idx * 2;
                __nv_bfloat162* d1 = (__nv_bfloat162*)(Hs + s1N) + idx * 2;
                d2[0] = __floats2bfloat162_rn(v2.x, v2.y);
                d2[1] = __floats2bfloat162_rn(v2.z, v2.w);
                d1[0] = __floats2bfloat162_rn(v1.x, v1.y);
                d1[1] = __floats2bfloat162_rn(v1.z, v1.w);
                ((float4*)XPs)[idx] = vp;
            }
        }
        __syncthreads();

        // ---- step a: LEd = pre(d>=2) + d1 + d0 ----
        float c = 0.f;
        if (lane < n0) c  = w0r * __bfloat162float(Hs[s1N + j0r]);
        if (lane < n1) c += w1r * __bfloat162float(Hs[s2N + j1r]);
        float LEd_a = pre_a + warp_sum(c);

        float r2 = x * x + y * y;
        float dxa = (-0.5f - r2) * x - 10.f * y + Gn * LEd_a - grs * x + GK * uA;
        float dya = (-0.5f - r2) * y + 10.f * x;
        float xa = x + DT * dxa + nsA.x;
        float ya = y + DT * dya + nsA.y;

        // ---- reconstruct x_j(a) for my d0 / d1 neighbor rows (exact) ----
        float xr0 = 0.f, xr1 = 0.f;
        if (lane < n0 && slot0 < SLOTCAP) {
            float acc = 0.f;
            int n = tabn[slot0];
            for (int m = 0; m < n; m++)
                acc = fmaf(__bfloat162float(tabw[slot0 * D0ROW + m]),
                           __bfloat162float(Hs[s1N + tabk[slot0 * D0ROW + m]]), acc);
            xr0 = XPs[j0r] + kappa * acc;
        }
        if (lane < n1 && slot1 < SLOTCAP) {
            float acc = 0.f;
            int n = tabn[slot1];
            for (int m = 0; m < n; m++)
                acc = fmaf(__bfloat162float(tabw[slot1 * D0ROW + m]),
                           __bfloat162float(Hs[s1N + tabk[slot1 * D0ROW + m]]), acc);
            xr1 = XPs[j1r] + kappa * acc;
        }

        // ---- step b: full gather (d>=1 incl d1 from Hs) + d0 from recon ----
        const int baseNb = (a % BUF) * NN;       // slot(a) [stale, weight 0 for d0]
        {
            float acc0 = 0.f, acc1 = 0.f;
            #pragma unroll
            for (int k = 0; k < KPL; k++) {
                int sN = baseNb - dNN[k];
                if (sN < 0) sN += BUF * NN;
                float h = __bfloat162float(Hs[sN + lane + 32 * k]);
                if (k & 1) acc1 = fmaf(wreg[k], h, acc1); else acc0 = fmaf(wreg[k], h, acc0);
            }
            float c0b = (lane < n0) ? w0r * xr0 : 0.f;
            float LEd_b = warp_sum(acc0 + acc1 + c0b);

            float r2b = xa * xa + ya * ya;
            float dxb = (-0.5f - r2b) * xa - 10.f * ya + Gn * LEd_b - grs * xa + GK * uB;
            float dyb = (-0.5f - r2b) * ya + 10.f * xa;
            x = xa + DT * dxb + nsB.x;
            y = ya + DT * dyb + nsB.y;
        }

        // ---- lookahead x_pre(b+1) and publish ----
        if (r + 1 < ROUNDS) {
            const int baseNp = (b % BUF) * NN;   // slot(b) [stale; d0,d1 masked]
            float acc0 = 0.f, acc1 = 0.f;
            #pragma unroll
            for (int k = 0; k < KPL; k++) {
                float w2 = ((mask1 >> k) & 1u) ? 0.f : wreg[k];
                int sN = baseNp - dNN[k];
                if (sN < 0) sN += BUF * NN;
                float h = __bfloat162float(Hs[sN + lane + 32 * k]);
                if (k & 1) acc1 = fmaf(w2, h, acc1); else acc0 = fmaf(w2, h, acc0);
            }
            float d1t = (lane < n1) ? w1r * xr1 : 0.f;
            float G2 = warp_sum(acc0 + acc1 + d1t);

            float r2c = x * x + y * y;
            float dxp = (-0.5f - r2c) * x - 10.f * y + Gn * G2 - grs * x + GK * uN;
            float xp = x + DT * dxp + nsN.x;

            if (lane == 0) {
                __stcg(&g_Xpub[par][i], xa);
                __stcg(&g_Xpub[par][NN + i], x);
                __stcg(&g_XPpub[par][i], xp);
            }
            __syncthreads();
            if (tid == 0) red_release(&g_ctr[r]);
        }

        // ---- tail: outputs, prefetch, partial gather for next a ----
        if (lane == 0 && (r % 5) == 4)
            g_XTR[(b / SPT) * NN + i] = x;

        if (r + 1 < ROUNDS) {
            int ta = 2 * r + 2, tb = 2 * r + 3, tn = 2 * r + 4;
            uA = uN; nsA = nsN;
            uB = __ldg(&external[i * (SPT * TRS) + (tb % SPT) * TRS + (tb / SPT)]);
            nsB = *(const float2*)&noise[(size_t)tb * 2 * NN + 2 * i];
            if (tn < TT) {
                uN = __ldg(&external[i * (SPT * TRS) + (tn % SPT) * TRS + (tn / SPT)]);
                nsN = *(const float2*)&noise[(size_t)tn * 2 * NN + 2 * i];
            }
            // partial gather for step ta: base slot(ta-1)=slot(b); d0,d1 masked
            const int baseNn = (b % BUF) * NN;
            float acc0 = 0.f, acc1 = 0.f;
            #pragma unroll
            for (int k = 0; k < KPL; k++) {
                float w2 = ((mask1 >> k) & 1u) ? 0.f : wreg[k];
                int sN = baseNn - dNN[k];
                if (sN < 0) sN += BUF * NN;
                float h = __bfloat162float(Hs[sN + lane + 32 * k]);
                if (k & 1) acc1 = fmaf(w2, h, acc1); else acc0 = fmaf(w2, h, acc0);
            }
            pre_a = warp_sum(acc0 + acc1);
        }
    }
}

// ---------------- EEG projection ----------------------------------------------
__global__ void k_eeg(const float* __restrict__ lm, float* __restrict__ out) {
    int c = blockIdx.x, tr = blockIdx.y, tid = threadIdx.x;
    float s = 0.f;
    for (int i = tid; i < NN; i += 128)
        s += g_XTR[tr * NN + i] * lm[c * NN + i];
    s = warp_sum(s);
    __shared__ float sh[4];
    if ((tid & 31) == 0) sh[tid >> 5] = s;
    __syncthreads();
    if (tid == 0) out[c * TRS + tr] = 5.0f * (sh[0] + sh[1] + sh[2] + sh[3]) - 2.0f;
}

extern "C" void kernel_launch(void* const* d_in, const int* in_sizes, int n_in,
                              void* d_out, int out_size) {
    const float* external = (const float*)d_in[0];
    const float* hx       = (const float*)d_in[1];
    const float* hE       = (const float*)d_in[2];
    const float* sc       = (const float*)d_in[3];
    const float* lm       = (const float*)d_in[4];
    const float* noise    = (const float*)d_in[5];
    const void*  delays   = d_in[6];

    const int smem = HBYTES + NN * 4                 // XPs
                   + RPB * 32 * 4 * 4                // j0,w0,j1,w1
                   + 2 * RPB * 4                     // counts
                   + SLOTCAP * 4                     // tabn
                   + SLOTCAP * D0ROW * 2             // tabk
                   + SLOTCAP * D0ROW * 2;            // tabw
    cudaFuncSetAttribute(k_main, cudaFuncAttributeMaxDynamicSharedMemorySize, smem);

    k_rowstats<<<NN, 128>>>(sc);
    k_prep2<<<(BUF * NN + 255) / 256, 256>>>(hE, delays);
    k_d0tab<<<(NN + 255) / 256, 256>>>(sc, delays);
    k_norm<<<1, 256>>>();
    k_xpre0<<<NN, 256>>>(hE, hx, sc, noise, external, delays);
    k_main<<<NBLK, THREADS, smem>>>(external, hx, sc, noise, delays);
    k_eeg<<<dim3(CC, TRS), 128>>>(lm, (float*)d_out);
}